// round 8
// baseline (speedup 1.0000x reference)
#include <cuda_runtime.h>
#include <cuda_bf16.h>
#include <cstdint>

#define HIDDEN   256
#define M_TILE   128
#define KC       64      // K elems per chunk (64 bf16 = 128B row = one SW128 atom)
#define NCHUNK   4
#define THREADS  256

// ---------------- smem layout ----------------
// per stage: Whi 32KB | Wlo 32KB | Xhi 16KB | Xlo 16KB = 96KB; 2 stages + bias
#define STAGE_STRIDE 98304
#define OFF_WHI  0
#define OFF_WLO  32768
#define OFF_XHI  65536
#define OFF_XLO  81920
#define OFF_BIAS 196608
#define SMEM_BYTES 197632

// Pre-swizzled W chunk images: [chunk][256 n-rows x 64 k-cols bf16, SW128] = 32KB/chunk
__device__ __align__(128) unsigned char g_Whi[NCHUNK * 32768];
__device__ __align__(128) unsigned char g_Wlo[NCHUNK * 32768];

// ---------------- helpers ----------------
__device__ __forceinline__ uint32_t sw128(uint32_t off) { return off ^ ((off >> 3) & 0x70); }

__device__ __forceinline__ uint32_t smem_u32(const void* p) {
    uint32_t a;
    asm("{ .reg .u64 t; cvta.to.shared.u64 t, %1; cvt.u32.u64 %0, t; }" : "=r"(a) : "l"(p));
    return a;
}

__device__ __forceinline__ void cp_async16(uint32_t saddr, const void* gaddr) {
    asm volatile("cp.async.cg.shared.global [%0], [%1], 16;" :: "r"(saddr), "l"(gaddr));
}

__device__ __forceinline__ void ldsm_x4(uint32_t* r, uint32_t addr) {
    asm volatile("ldmatrix.sync.aligned.m8n8.x4.shared.b16 {%0,%1,%2,%3}, [%4];"
                 : "=r"(r[0]), "=r"(r[1]), "=r"(r[2]), "=r"(r[3]) : "r"(addr));
}

__device__ __forceinline__ void mma_bf16(float* d, const uint32_t* a, uint32_t b0, uint32_t b1) {
    asm volatile(
        "mma.sync.aligned.m16n8k16.row.col.f32.bf16.bf16.f32 "
        "{%0,%1,%2,%3}, {%4,%5,%6,%7}, {%8,%9}, {%0,%1,%2,%3};"
        : "+f"(d[0]), "+f"(d[1]), "+f"(d[2]), "+f"(d[3])
        : "r"(a[0]), "r"(a[1]), "r"(a[2]), "r"(a[3]), "r"(b0), "r"(b1));
}

__device__ __forceinline__ float fast_tanh(float x) {
    // tanh(x) = 1 - 2/(e^{2x}+1); exact limits at +/-inf, ~1e-6 rel err otherwise
    float e;
    asm("ex2.approx.f32 %0, %1;" : "=f"(e) : "f"(x * 2.8853900817779268f));
    float r;
    asm("rcp.approx.f32 %0, %1;" : "=f"(r) : "f"(e + 1.0f));
    return fmaf(-2.0f, r, 1.0f);
}

__device__ __forceinline__ uint32_t pack_bf16(__nv_bfloat16 lo, __nv_bfloat16 hi) {
    return ((uint32_t)__bfloat16_as_ushort(hi) << 16) | __bfloat16_as_ushort(lo);
}

__device__ __forceinline__ void split_sts(float4 v, uint32_t ha, uint32_t la) {
    __nv_bfloat16 h0 = __float2bfloat16_rn(v.x);
    __nv_bfloat16 h1 = __float2bfloat16_rn(v.y);
    __nv_bfloat16 h2 = __float2bfloat16_rn(v.z);
    __nv_bfloat16 h3 = __float2bfloat16_rn(v.w);
    __nv_bfloat16 l0 = __float2bfloat16_rn(v.x - __bfloat162float(h0));
    __nv_bfloat16 l1 = __float2bfloat16_rn(v.y - __bfloat162float(h1));
    __nv_bfloat16 l2 = __float2bfloat16_rn(v.z - __bfloat162float(h2));
    __nv_bfloat16 l3 = __float2bfloat16_rn(v.w - __bfloat162float(h3));
    uint32_t hi01 = pack_bf16(h0, h1), hi23 = pack_bf16(h2, h3);
    uint32_t lo01 = pack_bf16(l0, l1), lo23 = pack_bf16(l2, l3);
    asm volatile("st.shared.v2.b32 [%0], {%1,%2};" :: "r"(ha), "r"(hi01), "r"(hi23) : "memory");
    asm volatile("st.shared.v2.b32 [%0], {%1,%2};" :: "r"(la), "r"(lo01), "r"(lo23) : "memory");
}

// ---------------- W prep: fp32 -> bf16 hi/lo, pre-swizzled per K-chunk ----------------
__global__ void prep_w_kernel(const float* __restrict__ W) {
    int idx = blockIdx.x * blockDim.x + threadIdx.x;   // 65536 elems
    int n = idx >> 8;
    int k = idx & 255;
    float w = W[idx];
    __nv_bfloat16 hi = __float2bfloat16_rn(w);
    __nv_bfloat16 lo = __float2bfloat16_rn(w - __bfloat162float(hi));
    int chunk = k >> 6, col = k & 63;
    uint32_t off = (uint32_t)chunk * 32768u + sw128((uint32_t)n * 128u + (uint32_t)col * 2u);
    *reinterpret_cast<__nv_bfloat16*>(g_Whi + off) = hi;
    *reinterpret_cast<__nv_bfloat16*>(g_Wlo + off) = lo;
}

// ---------------- main GEMM + tanh (mma.sync HMMA path) ----------------
__global__ void __launch_bounds__(THREADS, 1)
rotor_gemm_kernel(const float* __restrict__ x, const float* __restrict__ bias,
                  float* __restrict__ out) {
    extern __shared__ char smem[];
    const uint32_t sb = smem_u32(smem);
    const int tid = threadIdx.x;
    const int lane = tid & 31;
    const int wid = tid >> 5;
    const int warp_m = wid & 1;        // 2 m-blocks of 64
    const int warp_n = wid >> 1;       // 4 n-blocks of 64
    const int m_base = blockIdx.x * M_TILE;

    float* sbias = reinterpret_cast<float*>(smem + OFF_BIAS);
    sbias[tid] = bias[tid];            // 256 threads, 256 elems

    float acc[4][8][4];
    #pragma unroll
    for (int mi = 0; mi < 4; mi++)
        #pragma unroll
        for (int j = 0; j < 8; j++)
            #pragma unroll
            for (int q = 0; q < 4; q++) acc[mi][j][q] = 0.0f;

    // lane-derived addressing (SW128 on 128B rows: mask = (row&7)<<4, rows 8-aligned)
    const uint32_t maskS  = (uint32_t)(lane & 7) << 4;
    const uint32_t rowA   = (uint32_t)(warp_m * 8192 + (lane & 15) * 128);
    const uint32_t koffA  = (uint32_t)((lane >> 4) << 4);
    const uint32_t rowB   = (uint32_t)((warp_n * 64 + 8 * (lane >> 4) + (lane & 7)) * 128);
    const uint32_t koffB  = (uint32_t)(((lane >> 3) & 1) << 4);

    // ---- prologue: stage 0 <- chunk 0 ----
    {
        const char* gh = (const char*)g_Whi;
        const char* gl = (const char*)g_Wlo;
        #pragma unroll
        for (int i = 0; i < 8; i++) {
            uint32_t doff = (uint32_t)(tid + i * 256) * 16u;
            cp_async16(sb + OFF_WHI + doff, gh + doff);
            cp_async16(sb + OFF_WLO + doff, gl + doff);
        }
        asm volatile("cp.async.commit_group;" ::: "memory");
        #pragma unroll
        for (int i = 0; i < 8; i++) {
            int idx = tid + i * 256;
            int row = idx >> 4, c16 = idx & 15;
            float4 v = *reinterpret_cast<const float4*>(
                x + (size_t)(m_base + row) * HIDDEN + c16 * 4);
            uint32_t swoff = (uint32_t)(row * 128) +
                             (((uint32_t)(c16 * 8)) ^ ((uint32_t)(row & 7) << 4));
            split_sts(v, sb + OFF_XHI + swoff, sb + OFF_XLO + swoff);
        }
        asm volatile("cp.async.wait_group 0;" ::: "memory");
        __syncthreads();
    }

    #pragma unroll 1
    for (int c = 0; c < NCHUNK; c++) {
        const uint32_t sbase = sb + (uint32_t)(c & 1) * STAGE_STRIDE;
        const uint32_t nbase = sb + (uint32_t)((c & 1) ^ 1) * STAGE_STRIDE;

        float4 xr[8];
        if (c < NCHUNK - 1) {
            const char* gh = (const char*)g_Whi + (c + 1) * 32768;
            const char* gl = (const char*)g_Wlo + (c + 1) * 32768;
            #pragma unroll
            for (int i = 0; i < 8; i++) {
                uint32_t doff = (uint32_t)(tid + i * 256) * 16u;
                cp_async16(nbase + OFF_WHI + doff, gh + doff);
                cp_async16(nbase + OFF_WLO + doff, gl + doff);
            }
            asm volatile("cp.async.commit_group;" ::: "memory");
            #pragma unroll
            for (int i = 0; i < 8; i++) {
                int idx = tid + i * 256;
                int row = idx >> 4, c16 = idx & 15;
                xr[i] = *reinterpret_cast<const float4*>(
                    x + (size_t)(m_base + row) * HIDDEN + (c + 1) * KC + c16 * 4);
            }
        }

        // ---- compute chunk c: 4 k16-steps x (hh + lh + hl) ----
        const uint32_t xh = sbase + OFF_XHI, xl = sbase + OFF_XLO;
        const uint32_t wh = sbase + OFF_WHI, wl = sbase + OFF_WLO;
        #pragma unroll
        for (int kk = 0; kk < 4; kk++) {
            const uint32_t kA = (((uint32_t)kk * 32) + koffA) ^ maskS;
            const uint32_t kB = (((uint32_t)kk * 32) + koffB) ^ maskS;

            uint32_t ah[4][4], bh[4][4];
            #pragma unroll
            for (int mi = 0; mi < 4; mi++) ldsm_x4(ah[mi], xh + rowA + mi * 2048 + kA);
            #pragma unroll
            for (int jp = 0; jp < 4; jp++) ldsm_x4(bh[jp], wh + rowB + jp * 2048 + kB);

            // hh
            #pragma unroll
            for (int mi = 0; mi < 4; mi++)
                #pragma unroll
                for (int j = 0; j < 8; j++)
                    mma_bf16(acc[mi][j], ah[mi], bh[j >> 1][(j & 1) * 2], bh[j >> 1][(j & 1) * 2 + 1]);

            // lh (xl * Wh)
            {
                uint32_t al[4][4];
                #pragma unroll
                for (int mi = 0; mi < 4; mi++) ldsm_x4(al[mi], xl + rowA + mi * 2048 + kA);
                #pragma unroll
                for (int mi = 0; mi < 4; mi++)
                    #pragma unroll
                    for (int j = 0; j < 8; j++)
                        mma_bf16(acc[mi][j], al[mi], bh[j >> 1][(j & 1) * 2], bh[j >> 1][(j & 1) * 2 + 1]);
            }

            // hl (xh * Wl)
            {
                uint32_t bl[4][4];
                #pragma unroll
                for (int jp = 0; jp < 4; jp++) ldsm_x4(bl[jp], wl + rowB + jp * 2048 + kB);
                #pragma unroll
                for (int mi = 0; mi < 4; mi++)
                    #pragma unroll
                    for (int j = 0; j < 8; j++)
                        mma_bf16(acc[mi][j], ah[mi], bl[j >> 1][(j & 1) * 2], bl[j >> 1][(j & 1) * 2 + 1]);
            }
        }

        if (c < NCHUNK - 1) {
            #pragma unroll
            for (int i = 0; i < 8; i++) {
                int idx = tid + i * 256;
                int row = idx >> 4, c16 = idx & 15;
                uint32_t swoff = (uint32_t)(row * 128) +
                                 (((uint32_t)(c16 * 8)) ^ ((uint32_t)(row & 7) << 4));
                split_sts(xr[i], nbase + OFF_XHI + swoff, nbase + OFF_XLO + swoff);
            }
            asm volatile("cp.async.wait_group 0;" ::: "memory");
        }
        __syncthreads();
    }

    // ---- epilogue: bias + tanh + STG (32B-segment coalesced) ----
    #pragma unroll
    for (int mi = 0; mi < 4; mi++) {
        const int r0 = m_base + warp_m * 64 + mi * 16 + (lane >> 2);
        #pragma unroll
        for (int j = 0; j < 8; j++) {
            const int col = warp_n * 64 + 8 * j + 2 * (lane & 3);
            float b0 = sbias[col], b1 = sbias[col + 1];
            float2 v0 = make_float2(fast_tanh(acc[mi][j][0] + b0),
                                    fast_tanh(acc[mi][j][1] + b1));
            float2 v1 = make_float2(fast_tanh(acc[mi][j][2] + b0),
                                    fast_tanh(acc[mi][j][3] + b1));
            *reinterpret_cast<float2*>(out + (size_t)r0 * HIDDEN + col) = v0;
            *reinterpret_cast<float2*>(out + (size_t)(r0 + 8) * HIDDEN + col) = v1;
        }
    }
}

// ---------------- launch ----------------
extern "C" void kernel_launch(void* const* d_in, const int* in_sizes, int n_in,
                              void* d_out, int out_size) {
    const float* x = nullptr;
    const float* W = nullptr;
    const float* b = nullptr;
    for (int i = 0; i < n_in; i++) {
        if (in_sizes[i] == HIDDEN * HIDDEN)      W = (const float*)d_in[i];
        else if (in_sizes[i] == HIDDEN)          b = (const float*)d_in[i];
        else                                     x = (const float*)d_in[i];
    }
    float* out = (float*)d_out;
    int tokens = out_size / HIDDEN;   // 131072

    cudaFuncSetAttribute(rotor_gemm_kernel,
                         cudaFuncAttributeMaxDynamicSharedMemorySize, SMEM_BYTES);

    prep_w_kernel<<<(HIDDEN * HIDDEN) / 256, 256>>>(W);
    rotor_gemm_kernel<<<tokens / M_TILE, THREADS, SMEM_BYTES>>>(x, b, out);
}

// round 9
// speedup vs baseline: 1.1188x; 1.1188x over previous
#include <cuda_runtime.h>
#include <cuda_bf16.h>
#include <cstdint>

#define HIDDEN   256
#define M_TILE   64
#define KC       32      // K elems per chunk (32 bf16 = 64B row, SW64 swizzle)
#define NCHUNK   8
#define THREADS  256

// ---------------- smem layout ----------------
// per stage: Whi 16KB | Wlo 16KB | Xhi 4KB | Xlo 4KB = 40KB; 2 stages + bias
// total 81KB/CTA -> 2 CTAs/SM
#define STAGE_STRIDE 40960
#define OFF_WHI  0
#define OFF_WLO  16384
#define OFF_XHI  32768
#define OFF_XLO  36864
#define OFF_BIAS 81920
#define SMEM_BYTES 82944

// Pre-swizzled W chunk images: [chunk][256 n-rows x 32 k-cols bf16, SW64] = 16KB/chunk
__device__ __align__(128) unsigned char g_Whi[NCHUNK * 16384];
__device__ __align__(128) unsigned char g_Wlo[NCHUNK * 16384];

// ---------------- helpers ----------------
// SW64 swizzle for 64B rows: phys = row*64 + (cbytes ^ (((row>>1)&3)<<4))
__device__ __forceinline__ uint32_t sw64_mask(uint32_t row) { return ((row >> 1) & 3u) << 4; }

__device__ __forceinline__ uint32_t smem_u32(const void* p) {
    uint32_t a;
    asm("{ .reg .u64 t; cvta.to.shared.u64 t, %1; cvt.u32.u64 %0, t; }" : "=r"(a) : "l"(p));
    return a;
}

__device__ __forceinline__ void cp_async16(uint32_t saddr, const void* gaddr) {
    asm volatile("cp.async.cg.shared.global [%0], [%1], 16;" :: "r"(saddr), "l"(gaddr));
}

__device__ __forceinline__ void ldsm_x4(uint32_t* r, uint32_t addr) {
    asm volatile("ldmatrix.sync.aligned.m8n8.x4.shared.b16 {%0,%1,%2,%3}, [%4];"
                 : "=r"(r[0]), "=r"(r[1]), "=r"(r[2]), "=r"(r[3]) : "r"(addr));
}

__device__ __forceinline__ void mma_bf16(float* d, const uint32_t* a, uint32_t b0, uint32_t b1) {
    asm volatile(
        "mma.sync.aligned.m16n8k16.row.col.f32.bf16.bf16.f32 "
        "{%0,%1,%2,%3}, {%4,%5,%6,%7}, {%8,%9}, {%0,%1,%2,%3};"
        : "+f"(d[0]), "+f"(d[1]), "+f"(d[2]), "+f"(d[3])
        : "r"(a[0]), "r"(a[1]), "r"(a[2]), "r"(a[3]), "r"(b0), "r"(b1));
}

__device__ __forceinline__ float fast_tanh(float x) {
    // tanh(x) = 1 - 2/(e^{2x}+1); exact limits at +/-inf, ~1e-6 rel err otherwise
    float e;
    asm("ex2.approx.f32 %0, %1;" : "=f"(e) : "f"(x * 2.8853900817779268f));
    float r;
    asm("rcp.approx.f32 %0, %1;" : "=f"(r) : "f"(e + 1.0f));
    return fmaf(-2.0f, r, 1.0f);
}

__device__ __forceinline__ uint32_t pack_bf16(__nv_bfloat16 lo, __nv_bfloat16 hi) {
    return ((uint32_t)__bfloat16_as_ushort(hi) << 16) | __bfloat16_as_ushort(lo);
}

__device__ __forceinline__ void split_sts(float4 v, uint32_t ha, uint32_t la) {
    __nv_bfloat16 h0 = __float2bfloat16_rn(v.x);
    __nv_bfloat16 h1 = __float2bfloat16_rn(v.y);
    __nv_bfloat16 h2 = __float2bfloat16_rn(v.z);
    __nv_bfloat16 h3 = __float2bfloat16_rn(v.w);
    __nv_bfloat16 l0 = __float2bfloat16_rn(v.x - __bfloat162float(h0));
    __nv_bfloat16 l1 = __float2bfloat16_rn(v.y - __bfloat162float(h1));
    __nv_bfloat16 l2 = __float2bfloat16_rn(v.z - __bfloat162float(h2));
    __nv_bfloat16 l3 = __float2bfloat16_rn(v.w - __bfloat162float(h3));
    uint32_t hi01 = pack_bf16(h0, h1), hi23 = pack_bf16(h2, h3);
    uint32_t lo01 = pack_bf16(l0, l1), lo23 = pack_bf16(l2, l3);
    asm volatile("st.shared.v2.b32 [%0], {%1,%2};" :: "r"(ha), "r"(hi01), "r"(hi23) : "memory");
    asm volatile("st.shared.v2.b32 [%0], {%1,%2};" :: "r"(la), "r"(lo01), "r"(lo23) : "memory");
}

// ---------------- W prep: fp32 -> bf16 hi/lo, pre-swizzled per K-chunk (SW64) ----------------
__global__ void prep_w_kernel(const float* __restrict__ W) {
    int idx = blockIdx.x * blockDim.x + threadIdx.x;   // 65536 elems
    int n = idx >> 8;
    int k = idx & 255;
    float w = W[idx];
    __nv_bfloat16 hi = __float2bfloat16_rn(w);
    __nv_bfloat16 lo = __float2bfloat16_rn(w - __bfloat162float(hi));
    int chunk = k >> 5, col = k & 31;
    uint32_t off = (uint32_t)chunk * 16384u + (uint32_t)n * 64u
                 + (((uint32_t)col * 2u) ^ sw64_mask((uint32_t)n));
    *reinterpret_cast<__nv_bfloat16*>(g_Whi + off) = hi;
    *reinterpret_cast<__nv_bfloat16*>(g_Wlo + off) = lo;
}

// ---------------- main GEMM + tanh (mma.sync HMMA, occ 2) ----------------
__global__ void __launch_bounds__(THREADS, 2)
rotor_gemm_kernel(const float* __restrict__ x, const float* __restrict__ bias,
                  float* __restrict__ out) {
    extern __shared__ char smem[];
    const uint32_t sb = smem_u32(smem);
    const int tid = threadIdx.x;
    const int lane = tid & 31;
    const int wid = tid >> 5;
    const int warp_m = wid & 1;        // 2 m-blocks of 32
    const int warp_n = wid >> 1;       // 4 n-blocks of 64
    const int m_base = blockIdx.x * M_TILE;

    float* sbias = reinterpret_cast<float*>(smem + OFF_BIAS);
    sbias[tid] = bias[tid];            // 256 threads, 256 elems

    float acc[2][8][4];
    #pragma unroll
    for (int mi = 0; mi < 2; mi++)
        #pragma unroll
        for (int j = 0; j < 8; j++)
            #pragma unroll
            for (int q = 0; q < 4; q++) acc[mi][j][q] = 0.0f;

    // lane-derived addressing, SW64 swizzle (mask depends on row parity pair)
    const uint32_t maskS = ((uint32_t)(lane >> 1) & 3u) << 4;   // == ((row>>1)&3)<<4 for A and B rows
    const uint32_t rowA  = (uint32_t)(warp_m * 2048 + (lane & 15) * 64);
    const uint32_t koffA = (uint32_t)((lane >> 4) << 4);
    const uint32_t rowB  = (uint32_t)((warp_n * 64 + 8 * (lane >> 4) + (lane & 7)) * 64);
    const uint32_t koffB = (uint32_t)(((lane >> 3) & 1) << 4);

    // ---- prologue: stage 0 <- chunk 0 ----
    {
        const char* gh = (const char*)g_Whi;
        const char* gl = (const char*)g_Wlo;
        #pragma unroll
        for (int i = 0; i < 4; i++) {
            uint32_t doff = (uint32_t)(tid + i * 256) * 16u;
            cp_async16(sb + OFF_WHI + doff, gh + doff);
            cp_async16(sb + OFF_WLO + doff, gl + doff);
        }
        asm volatile("cp.async.commit_group;" ::: "memory");
        #pragma unroll
        for (int i = 0; i < 2; i++) {
            int idx = tid + i * 256;
            int row = idx >> 3, c8 = idx & 7;
            float4 v = *reinterpret_cast<const float4*>(
                x + (size_t)(m_base + row) * HIDDEN + c8 * 4);
            uint32_t swoff = (uint32_t)(row * 64) + (((uint32_t)(c8 * 8)) ^ sw64_mask((uint32_t)row));
            split_sts(v, sb + OFF_XHI + swoff, sb + OFF_XLO + swoff);
        }
        asm volatile("cp.async.wait_group 0;" ::: "memory");
        __syncthreads();
    }

    #pragma unroll 1
    for (int c = 0; c < NCHUNK; c++) {
        const uint32_t sbase = sb + (uint32_t)(c & 1) * STAGE_STRIDE;
        const uint32_t nbase = sb + (uint32_t)((c & 1) ^ 1) * STAGE_STRIDE;

        float4 xr[2];
        if (c < NCHUNK - 1) {
            const char* gh = (const char*)g_Whi + (c + 1) * 16384;
            const char* gl = (const char*)g_Wlo + (c + 1) * 16384;
            #pragma unroll
            for (int i = 0; i < 4; i++) {
                uint32_t doff = (uint32_t)(tid + i * 256) * 16u;
                cp_async16(nbase + OFF_WHI + doff, gh + doff);
                cp_async16(nbase + OFF_WLO + doff, gl + doff);
            }
            asm volatile("cp.async.commit_group;" ::: "memory");
            #pragma unroll
            for (int i = 0; i < 2; i++) {
                int idx = tid + i * 256;
                int row = idx >> 3, c8 = idx & 7;
                xr[i] = *reinterpret_cast<const float4*>(
                    x + (size_t)(m_base + row) * HIDDEN + (c + 1) * KC + c8 * 4);
            }
        }

        // ---- compute chunk c: 2 k16-steps x (hh + lh + hl) ----
        const uint32_t xh = sbase + OFF_XHI, xl = sbase + OFF_XLO;
        const uint32_t wh = sbase + OFF_WHI, wl = sbase + OFF_WLO;
        #pragma unroll
        for (int kk = 0; kk < 2; kk++) {
            const uint32_t kA = (((uint32_t)kk * 32) + koffA) ^ maskS;
            const uint32_t kB = (((uint32_t)kk * 32) + koffB) ^ maskS;

            uint32_t ah[2][4], bh[4][4];
            #pragma unroll
            for (int mi = 0; mi < 2; mi++) ldsm_x4(ah[mi], xh + rowA + mi * 1024 + kA);
            #pragma unroll
            for (int jp = 0; jp < 4; jp++) ldsm_x4(bh[jp], wh + rowB + jp * 1024 + kB);

            // hh
            #pragma unroll
            for (int mi = 0; mi < 2; mi++)
                #pragma unroll
                for (int j = 0; j < 8; j++)
                    mma_bf16(acc[mi][j], ah[mi], bh[j >> 1][(j & 1) * 2], bh[j >> 1][(j & 1) * 2 + 1]);

            // lh (xl * Wh)
            {
                uint32_t al[2][4];
                #pragma unroll
                for (int mi = 0; mi < 2; mi++) ldsm_x4(al[mi], xl + rowA + mi * 1024 + kA);
                #pragma unroll
                for (int mi = 0; mi < 2; mi++)
                    #pragma unroll
                    for (int j = 0; j < 8; j++)
                        mma_bf16(acc[mi][j], al[mi], bh[j >> 1][(j & 1) * 2], bh[j >> 1][(j & 1) * 2 + 1]);
            }

            // hl (xh * Wl)
            {
                uint32_t bl[4][4];
                #pragma unroll
                for (int jp = 0; jp < 4; jp++) ldsm_x4(bl[jp], wl + rowB + jp * 1024 + kB);
                #pragma unroll
                for (int mi = 0; mi < 2; mi++)
                    #pragma unroll
                    for (int j = 0; j < 8; j++)
                        mma_bf16(acc[mi][j], ah[mi], bl[j >> 1][(j & 1) * 2], bl[j >> 1][(j & 1) * 2 + 1]);
            }
        }

        if (c < NCHUNK - 1) {
            #pragma unroll
            for (int i = 0; i < 2; i++) {
                int idx = tid + i * 256;
                int row = idx >> 3, c8 = idx & 7;
                uint32_t swoff = (uint32_t)(row * 64) +
                                 (((uint32_t)(c8 * 8)) ^ sw64_mask((uint32_t)row));
                split_sts(xr[i], nbase + OFF_XHI + swoff, nbase + OFF_XLO + swoff);
            }
            asm volatile("cp.async.wait_group 0;" ::: "memory");
        }
        __syncthreads();
    }

    // ---- epilogue: bias + tanh + STG (32B-segment coalesced) ----
    #pragma unroll
    for (int mi = 0; mi < 2; mi++) {
        const int r0 = m_base + warp_m * 32 + mi * 16 + (lane >> 2);
        #pragma unroll
        for (int j = 0; j < 8; j++) {
            const int col = warp_n * 64 + 8 * j + 2 * (lane & 3);
            float b0 = sbias[col], b1 = sbias[col + 1];
            float2 v0 = make_float2(fast_tanh(acc[mi][j][0] + b0),
                                    fast_tanh(acc[mi][j][1] + b1));
            float2 v1 = make_float2(fast_tanh(acc[mi][j][2] + b0),
                                    fast_tanh(acc[mi][j][3] + b1));
            *reinterpret_cast<float2*>(out + (size_t)r0 * HIDDEN + col) = v0;
            *reinterpret_cast<float2*>(out + (size_t)(r0 + 8) * HIDDEN + col) = v1;
        }
    }
}

// ---------------- launch ----------------
extern "C" void kernel_launch(void* const* d_in, const int* in_sizes, int n_in,
                              void* d_out, int out_size) {
    const float* x = nullptr;
    const float* W = nullptr;
    const float* b = nullptr;
    for (int i = 0; i < n_in; i++) {
        if (in_sizes[i] == HIDDEN * HIDDEN)      W = (const float*)d_in[i];
        else if (in_sizes[i] == HIDDEN)          b = (const float*)d_in[i];
        else                                     x = (const float*)d_in[i];
    }
    float* out = (float*)d_out;
    int tokens = out_size / HIDDEN;   // 131072

    cudaFuncSetAttribute(rotor_gemm_kernel,
                         cudaFuncAttributeMaxDynamicSharedMemorySize, SMEM_BYTES);

    prep_w_kernel<<<(HIDDEN * HIDDEN) / 256, 256>>>(W);
    rotor_gemm_kernel<<<tokens / M_TILE, THREADS, SMEM_BYTES>>>(x, b, out);
}

// round 14
// speedup vs baseline: 1.4808x; 1.3235x over previous
#include <cuda_runtime.h>
#include <cuda_fp16.h>
#include <cstdint>

#define HIDDEN   256
#define M_TILE   64
#define KC       64      // K elems per chunk (64 fp16 = 128B row, SW128)
#define NCHUNK   4
#define THREADS  256

// ---------------- smem layout ----------------
// per stage: W 32KB | Xh 8KB | Xl 8KB = 48KB; 2 stages + bias = ~97KB -> 2 CTAs/SM
#define STAGE_STRIDE 49152
#define OFF_W    0
#define OFF_XH   32768
#define OFF_XL   40960
#define OFF_BIAS 98304
#define SMEM_BYTES 99328

// Pre-swizzled W chunk images: [chunk][256 n-rows x 64 k-cols fp16, SW128] = 32KB/chunk
__device__ __align__(128) unsigned char g_W[NCHUNK * 32768];

// ---------------- helpers ----------------
__device__ __forceinline__ uint32_t sw128(uint32_t off) { return off ^ ((off >> 3) & 0x70); }

__device__ __forceinline__ uint32_t smem_u32(const void* p) {
    uint32_t a;
    asm("{ .reg .u64 t; cvta.to.shared.u64 t, %1; cvt.u32.u64 %0, t; }" : "=r"(a) : "l"(p));
    return a;
}

__device__ __forceinline__ void cp_async16(uint32_t saddr, const void* gaddr) {
    asm volatile("cp.async.cg.shared.global [%0], [%1], 16;" :: "r"(saddr), "l"(gaddr));
}

__device__ __forceinline__ void ldsm_x4(uint32_t* r, uint32_t addr) {
    asm volatile("ldmatrix.sync.aligned.m8n8.x4.shared.b16 {%0,%1,%2,%3}, [%4];"
                 : "=r"(r[0]), "=r"(r[1]), "=r"(r[2]), "=r"(r[3]) : "r"(addr));
}

__device__ __forceinline__ void mma_f16(float* d, const uint32_t* a, uint32_t b0, uint32_t b1) {
    asm volatile(
        "mma.sync.aligned.m16n8k16.row.col.f32.f16.f16.f32 "
        "{%0,%1,%2,%3}, {%4,%5,%6,%7}, {%8,%9}, {%0,%1,%2,%3};"
        : "+f"(d[0]), "+f"(d[1]), "+f"(d[2]), "+f"(d[3])
        : "r"(a[0]), "r"(a[1]), "r"(a[2]), "r"(a[3]), "r"(b0), "r"(b1));
}

__device__ __forceinline__ float fast_tanh(float x) {
    // tanh(x) = 1 - 2/(e^{2x}+1); exact limits at +/-inf, ~1e-6 rel err otherwise
    float e;
    asm("ex2.approx.f32 %0, %1;" : "=f"(e) : "f"(x * 2.8853900817779268f));
    float r;
    asm("rcp.approx.f32 %0, %1;" : "=f"(r) : "f"(e + 1.0f));
    return fmaf(-2.0f, r, 1.0f);
}

__device__ __forceinline__ uint32_t pack_h2(__half lo, __half hi) {
    return ((uint32_t)__half_as_ushort(hi) << 16) | __half_as_ushort(lo);
}

// fp16 split: v = hi + lo, store hi quad + lo quad to swizzled smem
__device__ __forceinline__ void split_sts(float4 v, uint32_t ha, uint32_t la) {
    __half h0 = __float2half_rn(v.x);
    __half h1 = __float2half_rn(v.y);
    __half h2 = __float2half_rn(v.z);
    __half h3 = __float2half_rn(v.w);
    __half l0 = __float2half_rn(v.x - __half2float(h0));
    __half l1 = __float2half_rn(v.y - __half2float(h1));
    __half l2 = __float2half_rn(v.z - __half2float(h2));
    __half l3 = __float2half_rn(v.w - __half2float(h3));
    uint32_t hi01 = pack_h2(h0, h1), hi23 = pack_h2(h2, h3);
    uint32_t lo01 = pack_h2(l0, l1), lo23 = pack_h2(l2, l3);
    asm volatile("st.shared.v2.b32 [%0], {%1,%2};" :: "r"(ha), "r"(hi01), "r"(hi23) : "memory");
    asm volatile("st.shared.v2.b32 [%0], {%1,%2};" :: "r"(la), "r"(lo01), "r"(lo23) : "memory");
}

// ---------------- W prep: fp32 -> fp16, pre-swizzled per K-chunk (SW128) ----------------
__global__ void prep_w_kernel(const float* __restrict__ W) {
    int idx = blockIdx.x * blockDim.x + threadIdx.x;   // 65536 elems
    int n = idx >> 8;
    int k = idx & 255;
    __half h = __float2half_rn(W[idx]);
    int chunk = k >> 6, col = k & 63;
    uint32_t off = (uint32_t)chunk * 32768u + sw128((uint32_t)n * 128u + (uint32_t)col * 2u);
    *reinterpret_cast<__half*>(g_W + off) = h;
}

// ---------------- main GEMM + tanh (mma.sync fp16, 2-term, occ 2) ----------------
__global__ void __launch_bounds__(THREADS, 2)
rotor_gemm_kernel(const float* __restrict__ x, const float* __restrict__ bias,
                  float* __restrict__ out) {
    extern __shared__ char smem[];
    const uint32_t sb = smem_u32(smem);
    const int tid = threadIdx.x;
    const int lane = tid & 31;
    const int wid = tid >> 5;
    const int warp_m = wid & 1;        // 2 m-blocks of 32
    const int warp_n = wid >> 1;       // 4 n-blocks of 64
    const int m_base = blockIdx.x * M_TILE;

    float* sbias = reinterpret_cast<float*>(smem + OFF_BIAS);
    sbias[tid] = bias[tid];            // 256 threads, 256 elems

    float acc[2][8][4];
    #pragma unroll
    for (int mi = 0; mi < 2; mi++)
        #pragma unroll
        for (int j = 0; j < 8; j++)
            #pragma unroll
            for (int q = 0; q < 4; q++) acc[mi][j][q] = 0.0f;

    // lane-derived addressing (SW128 on 128B rows; proven in R8)
    const uint32_t maskS = (uint32_t)(lane & 7) << 4;
    const uint32_t rowA  = (uint32_t)(warp_m * 4096 + (lane & 15) * 128);   // 32 rows per warp_m
    const uint32_t koffA = (uint32_t)((lane >> 4) << 4);
    const uint32_t rowB  = (uint32_t)((warp_n * 64 + 8 * (lane >> 4) + (lane & 7)) * 128);
    const uint32_t koffB = (uint32_t)(((lane >> 3) & 1) << 4);

    // ---- prologue: stage 0 <- chunk 0 ----
    {
        const char* gw = (const char*)g_W;
        #pragma unroll
        for (int i = 0; i < 8; i++) {
            uint32_t doff = (uint32_t)(tid + i * 256) * 16u;
            cp_async16(sb + OFF_W + doff, gw + doff);
        }
        asm volatile("cp.async.commit_group;" ::: "memory");
        #pragma unroll
        for (int i = 0; i < 4; i++) {
            int idx = tid + i * 256;
            int row = idx >> 4, c16 = idx & 15;          // 64 rows x 16 float4
            float4 v = *reinterpret_cast<const float4*>(
                x + (size_t)(m_base + row) * HIDDEN + c16 * 4);
            uint32_t swoff = (uint32_t)(row * 128) +
                             (((uint32_t)(c16 * 8)) ^ ((uint32_t)(row & 7) << 4));
            split_sts(v, sb + OFF_XH + swoff, sb + OFF_XL + swoff);
        }
        asm volatile("cp.async.wait_group 0;" ::: "memory");
        __syncthreads();
    }

    #pragma unroll 1
    for (int c = 0; c < NCHUNK; c++) {
        const uint32_t sbase = sb + (uint32_t)(c & 1) * STAGE_STRIDE;
        const uint32_t nbase = sb + (uint32_t)((c & 1) ^ 1) * STAGE_STRIDE;

        float4 xr[4];
        if (c < NCHUNK - 1) {
            const char* gw = (const char*)g_W + (c + 1) * 32768;
            #pragma unroll
            for (int i = 0; i < 8; i++) {
                uint32_t doff = (uint32_t)(tid + i * 256) * 16u;
                cp_async16(nbase + OFF_W + doff, gw + doff);
            }
            asm volatile("cp.async.commit_group;" ::: "memory");
            #pragma unroll
            for (int i = 0; i < 4; i++) {
                int idx = tid + i * 256;
                int row = idx >> 4, c16 = idx & 15;
                xr[i] = *reinterpret_cast<const float4*>(
                    x + (size_t)(m_base + row) * HIDDEN + (c + 1) * KC + c16 * 4);
            }
        }

        // ---- compute chunk c: 4 k16-steps x (hh + lh) ----
        const uint32_t xh = sbase + OFF_XH, xl = sbase + OFF_XL;
        const uint32_t wb = sbase + OFF_W;
        #pragma unroll
        for (int kk = 0; kk < 4; kk++) {
            const uint32_t kA = (((uint32_t)kk * 32) + koffA) ^ maskS;
            const uint32_t kB = (((uint32_t)kk * 32) + koffB) ^ maskS;

            uint32_t ah[2][4], al[2][4], bh[4][4];
            #pragma unroll
            for (int mi = 0; mi < 2; mi++) ldsm_x4(ah[mi], xh + rowA + mi * 2048 + kA);
            #pragma unroll
            for (int jp = 0; jp < 4; jp++) ldsm_x4(bh[jp], wb + rowB + jp * 2048 + kB);
            #pragma unroll
            for (int mi = 0; mi < 2; mi++) ldsm_x4(al[mi], xl + rowA + mi * 2048 + kA);

            // hh: xh * W
            #pragma unroll
            for (int mi = 0; mi < 2; mi++)
                #pragma unroll
                for (int j = 0; j < 8; j++)
                    mma_f16(acc[mi][j], ah[mi], bh[j >> 1][(j & 1) * 2], bh[j >> 1][(j & 1) * 2 + 1]);

            // lh: xl * W
            #pragma unroll
            for (int mi = 0; mi < 2; mi++)
                #pragma unroll
                for (int j = 0; j < 8; j++)
                    mma_f16(acc[mi][j], al[mi], bh[j >> 1][(j & 1) * 2], bh[j >> 1][(j & 1) * 2 + 1]);
        }

        if (c < NCHUNK - 1) {
            #pragma unroll
            for (int i = 0; i < 4; i++) {
                int idx = tid + i * 256;
                int row = idx >> 4, c16 = idx & 15;
                uint32_t swoff = (uint32_t)(row * 128) +
                                 (((uint32_t)(c16 * 8)) ^ ((uint32_t)(row & 7) << 4));
                split_sts(xr[i], nbase + OFF_XH + swoff, nbase + OFF_XL + swoff);
            }
            asm volatile("cp.async.wait_group 0;" ::: "memory");
        }
        __syncthreads();
    }

    // ---- epilogue: bias + tanh + STG (32B-segment coalesced) ----
    #pragma unroll
    for (int mi = 0; mi < 2; mi++) {
        const int r0 = m_base + warp_m * 32 + mi * 16 + (lane >> 2);
        #pragma unroll
        for (int j = 0; j < 8; j++) {
            const int col = warp_n * 64 + 8 * j + 2 * (lane & 3);
            float b0 = sbias[col], b1 = sbias[col + 1];
            float2 v0 = make_float2(fast_tanh(acc[mi][j][0] + b0),
                                    fast_tanh(acc[mi][j][1] + b1));
            float2 v1 = make_float2(fast_tanh(acc[mi][j][2] + b0),
                                    fast_tanh(acc[mi][j][3] + b1));
            *reinterpret_cast<float2*>(out + (size_t)r0 * HIDDEN + col) = v0;
            *reinterpret_cast<float2*>(out + (size_t)(r0 + 8) * HIDDEN + col) = v1;
        }
    }
}

// ---------------- launch ----------------
extern "C" void kernel_launch(void* const* d_in, const int* in_sizes, int n_in,
                              void* d_out, int out_size) {
    const float* x = nullptr;
    const float* W = nullptr;
    const float* b = nullptr;
    for (int i = 0; i < n_in; i++) {
        if (in_sizes[i] == HIDDEN * HIDDEN)      W = (const float*)d_in[i];
        else if (in_sizes[i] == HIDDEN)          b = (const float*)d_in[i];
        else                                     x = (const float*)d_in[i];
    }
    float* out = (float*)d_out;
    int tokens = out_size / HIDDEN;   // 131072

    cudaFuncSetAttribute(rotor_gemm_kernel,
                         cudaFuncAttributeMaxDynamicSharedMemorySize, SMEM_BYTES);

    prep_w_kernel<<<(HIDDEN * HIDDEN) / 256, 256>>>(W);
    rotor_gemm_kernel<<<tokens / M_TILE, THREADS, SMEM_BYTES>>>(x, b, out);
}

// round 15
// speedup vs baseline: 1.9678x; 1.3288x over previous
#include <cuda_runtime.h>
#include <cuda_fp16.h>
#include <cstdint>

#define HIDDEN   256
#define M_TILE   64
#define KC       64      // K elems per chunk (64 fp16 = 128B row, SW128)
#define NCHUNK   4
#define THREADS  256

// ---------------- smem layout ----------------
// per stage: W 32KB | Xh 8KB = 40KB; 2 stages + bias = ~81KB -> 2 CTAs/SM (RF-capped anyway)
#define STAGE_STRIDE 40960
#define OFF_W    0
#define OFF_XH   32768
#define OFF_BIAS 81920
#define SMEM_BYTES 82944

// Pre-swizzled W chunk images: [chunk][256 n-rows x 64 k-cols fp16, SW128] = 32KB/chunk
__device__ __align__(128) unsigned char g_W[NCHUNK * 32768];

// ---------------- helpers ----------------
__device__ __forceinline__ uint32_t sw128(uint32_t off) { return off ^ ((off >> 3) & 0x70); }

__device__ __forceinline__ uint32_t smem_u32(const void* p) {
    uint32_t a;
    asm("{ .reg .u64 t; cvta.to.shared.u64 t, %1; cvt.u32.u64 %0, t; }" : "=r"(a) : "l"(p));
    return a;
}

__device__ __forceinline__ void cp_async16(uint32_t saddr, const void* gaddr) {
    asm volatile("cp.async.cg.shared.global [%0], [%1], 16;" :: "r"(saddr), "l"(gaddr));
}

__device__ __forceinline__ void ldsm_x4(uint32_t* r, uint32_t addr) {
    asm volatile("ldmatrix.sync.aligned.m8n8.x4.shared.b16 {%0,%1,%2,%3}, [%4];"
                 : "=r"(r[0]), "=r"(r[1]), "=r"(r[2]), "=r"(r[3]) : "r"(addr));
}

__device__ __forceinline__ void mma_f16(float* d, const uint32_t* a, uint32_t b0, uint32_t b1) {
    asm volatile(
        "mma.sync.aligned.m16n8k16.row.col.f32.f16.f16.f32 "
        "{%0,%1,%2,%3}, {%4,%5,%6,%7}, {%8,%9}, {%0,%1,%2,%3};"
        : "+f"(d[0]), "+f"(d[1]), "+f"(d[2]), "+f"(d[3])
        : "r"(a[0]), "r"(a[1]), "r"(a[2]), "r"(a[3]), "r"(b0), "r"(b1));
}

__device__ __forceinline__ float fast_tanh(float x) {
    // tanh(x) = 1 - 2/(e^{2x}+1); exact limits at +/-inf, ~1e-6 rel err otherwise
    float e;
    asm("ex2.approx.f32 %0, %1;" : "=f"(e) : "f"(x * 2.8853900817779268f));
    float r;
    asm("rcp.approx.f32 %0, %1;" : "=f"(r) : "f"(e + 1.0f));
    return fmaf(-2.0f, r, 1.0f);
}

__device__ __forceinline__ uint32_t pack_h2(__half lo, __half hi) {
    return ((uint32_t)__half_as_ushort(hi) << 16) | __half_as_ushort(lo);
}

// fp16 convert + store quad (single term: no lo half)
__device__ __forceinline__ void cvt_sts(float4 v, uint32_t ha) {
    uint32_t hi01 = pack_h2(__float2half_rn(v.x), __float2half_rn(v.y));
    uint32_t hi23 = pack_h2(__float2half_rn(v.z), __float2half_rn(v.w));
    asm volatile("st.shared.v2.b32 [%0], {%1,%2};" :: "r"(ha), "r"(hi01), "r"(hi23) : "memory");
}

// ---------------- W prep: fp32 -> fp16, pre-swizzled per K-chunk (SW128) ----------------
__global__ void prep_w_kernel(const float* __restrict__ W) {
    int idx = blockIdx.x * blockDim.x + threadIdx.x;   // 65536 elems
    int n = idx >> 8;
    int k = idx & 255;
    __half h = __float2half_rn(W[idx]);
    int chunk = k >> 6, col = k & 63;
    uint32_t off = (uint32_t)chunk * 32768u + sw128((uint32_t)n * 128u + (uint32_t)col * 2u);
    *reinterpret_cast<__half*>(g_W + off) = h;
}

// ---------------- main GEMM + tanh (mma.sync fp16, single-term, occ 2) ----------------
__global__ void __launch_bounds__(THREADS, 2)
rotor_gemm_kernel(const float* __restrict__ x, const float* __restrict__ bias,
                  float* __restrict__ out) {
    extern __shared__ char smem[];
    const uint32_t sb = smem_u32(smem);
    const int tid = threadIdx.x;
    const int lane = tid & 31;
    const int wid = tid >> 5;
    const int warp_m = wid & 1;        // 2 m-blocks of 32
    const int warp_n = wid >> 1;       // 4 n-blocks of 64
    const int m_base = blockIdx.x * M_TILE;

    float* sbias = reinterpret_cast<float*>(smem + OFF_BIAS);
    sbias[tid] = bias[tid];            // 256 threads, 256 elems

    float acc[2][8][4];
    #pragma unroll
    for (int mi = 0; mi < 2; mi++)
        #pragma unroll
        for (int j = 0; j < 8; j++)
            #pragma unroll
            for (int q = 0; q < 4; q++) acc[mi][j][q] = 0.0f;

    // lane-derived addressing (SW128 on 128B rows; proven since R8)
    const uint32_t maskS = (uint32_t)(lane & 7) << 4;
    const uint32_t rowA  = (uint32_t)(warp_m * 4096 + (lane & 15) * 128);   // 32 rows per warp_m
    const uint32_t koffA = (uint32_t)((lane >> 4) << 4);
    const uint32_t rowB  = (uint32_t)((warp_n * 64 + 8 * (lane >> 4) + (lane & 7)) * 128);
    const uint32_t koffB = (uint32_t)(((lane >> 3) & 1) << 4);

    // ---- prologue: stage 0 <- chunk 0 ----
    {
        const char* gw = (const char*)g_W;
        #pragma unroll
        for (int i = 0; i < 8; i++) {
            uint32_t doff = (uint32_t)(tid + i * 256) * 16u;
            cp_async16(sb + OFF_W + doff, gw + doff);
        }
        asm volatile("cp.async.commit_group;" ::: "memory");
        #pragma unroll
        for (int i = 0; i < 4; i++) {
            int idx = tid + i * 256;
            int row = idx >> 4, c16 = idx & 15;          // 64 rows x 16 float4
            float4 v = *reinterpret_cast<const float4*>(
                x + (size_t)(m_base + row) * HIDDEN + c16 * 4);
            uint32_t swoff = (uint32_t)(row * 128) +
                             (((uint32_t)(c16 * 8)) ^ ((uint32_t)(row & 7) << 4));
            cvt_sts(v, sb + OFF_XH + swoff);
        }
        asm volatile("cp.async.wait_group 0;" ::: "memory");
        __syncthreads();
    }

    #pragma unroll 1
    for (int c = 0; c < NCHUNK; c++) {
        const uint32_t sbase = sb + (uint32_t)(c & 1) * STAGE_STRIDE;
        const uint32_t nbase = sb + (uint32_t)((c & 1) ^ 1) * STAGE_STRIDE;

        float4 xr[4];
        if (c < NCHUNK - 1) {
            const char* gw = (const char*)g_W + (c + 1) * 32768;
            #pragma unroll
            for (int i = 0; i < 8; i++) {
                uint32_t doff = (uint32_t)(tid + i * 256) * 16u;
                cp_async16(nbase + OFF_W + doff, gw + doff);
            }
            asm volatile("cp.async.commit_group;" ::: "memory");
            #pragma unroll
            for (int i = 0; i < 4; i++) {
                int idx = tid + i * 256;
                int row = idx >> 4, c16 = idx & 15;
                xr[i] = *reinterpret_cast<const float4*>(
                    x + (size_t)(m_base + row) * HIDDEN + (c + 1) * KC + c16 * 4);
            }
        }

        // ---- compute chunk c: 4 k16-steps, single term ----
        const uint32_t xh = sbase + OFF_XH;
        const uint32_t wb = sbase + OFF_W;
        #pragma unroll
        for (int kk = 0; kk < 4; kk++) {
            const uint32_t kA = (((uint32_t)kk * 32) + koffA) ^ maskS;
            const uint32_t kB = (((uint32_t)kk * 32) + koffB) ^ maskS;

            uint32_t ah[2][4], bh[4][4];
            #pragma unroll
            for (int mi = 0; mi < 2; mi++) ldsm_x4(ah[mi], xh + rowA + mi * 2048 + kA);
            #pragma unroll
            for (int jp = 0; jp < 4; jp++) ldsm_x4(bh[jp], wb + rowB + jp * 2048 + kB);

            #pragma unroll
            for (int mi = 0; mi < 2; mi++)
                #pragma unroll
                for (int j = 0; j < 8; j++)
                    mma_f16(acc[mi][j], ah[mi], bh[j >> 1][(j & 1) * 2], bh[j >> 1][(j & 1) * 2 + 1]);
        }

        if (c < NCHUNK - 1) {
            #pragma unroll
            for (int i = 0; i < 4; i++) {
                int idx = tid + i * 256;
                int row = idx >> 4, c16 = idx & 15;
                uint32_t swoff = (uint32_t)(row * 128) +
                                 (((uint32_t)(c16 * 8)) ^ ((uint32_t)(row & 7) << 4));
                cvt_sts(xr[i], nbase + OFF_XH + swoff);
            }
            asm volatile("cp.async.wait_group 0;" ::: "memory");
        }
        __syncthreads();
    }

    // ---- epilogue: bias + tanh + STG (32B-segment coalesced) ----
    #pragma unroll
    for (int mi = 0; mi < 2; mi++) {
        const int r0 = m_base + warp_m * 32 + mi * 16 + (lane >> 2);
        #pragma unroll
        for (int j = 0; j < 8; j++) {
            const int col = warp_n * 64 + 8 * j + 2 * (lane & 3);
            float b0 = sbias[col], b1 = sbias[col + 1];
            float2 v0 = make_float2(fast_tanh(acc[mi][j][0] + b0),
                                    fast_tanh(acc[mi][j][1] + b1));
            float2 v1 = make_float2(fast_tanh(acc[mi][j][2] + b0),
                                    fast_tanh(acc[mi][j][3] + b1));
            *reinterpret_cast<float2*>(out + (size_t)r0 * HIDDEN + col) = v0;
            *reinterpret_cast<float2*>(out + (size_t)(r0 + 8) * HIDDEN + col) = v1;
        }
    }
}

// ---------------- launch ----------------
extern "C" void kernel_launch(void* const* d_in, const int* in_sizes, int n_in,
                              void* d_out, int out_size) {
    const float* x = nullptr;
    const float* W = nullptr;
    const float* b = nullptr;
    for (int i = 0; i < n_in; i++) {
        if (in_sizes[i] == HIDDEN * HIDDEN)      W = (const float*)d_in[i];
        else if (in_sizes[i] == HIDDEN)          b = (const float*)d_in[i];
        else                                     x = (const float*)d_in[i];
    }
    float* out = (float*)d_out;
    int tokens = out_size / HIDDEN;   // 131072

    cudaFuncSetAttribute(rotor_gemm_kernel,
                         cudaFuncAttributeMaxDynamicSharedMemorySize, SMEM_BYTES);

    prep_w_kernel<<<(HIDDEN * HIDDEN) / 256, 256>>>(W);
    rotor_gemm_kernel<<<tokens / M_TILE, THREADS, SMEM_BYTES>>>(x, b, out);
}